// round 2
// baseline (speedup 1.0000x reference)
#include <cuda_runtime.h>
#include <cstdint>

#define NBLOCKS   592
#define NTHREADS  256
#define TOTALT    (NBLOCKS * NTHREADS)          // 151552 threads
#define B_ROWS    4000000
#define RPT       ((B_ROWS + TOTALT - 1) / TOTALT)   // 27 rows per thread
#define MAXIT     100
#define SMEM_BYTES (2u * NTHREADS * RPT * sizeof(float))  // 55296 B

// ---- device-global state (reset by stk_init each launch so graph replays work) ----
__device__ double       g_accum[MAXIT];
__device__ unsigned int g_count;
__device__ unsigned int g_release;

__global__ void stk_init() {
    int i = threadIdx.x;
    for (int j = i; j < MAXIT; j += blockDim.x) g_accum[j] = 0.0;
    if (i == 0) { g_count = 0u; g_release = 0u; }
}

// Software grid barrier. Safe because grid is guaranteed fully co-resident:
// __launch_bounds__(256,4) caps regs at 64, smem 55.3KB*4 = 221KB <= 228KB/SM,
// 592 blocks <= 4 * 148 SMs (GB300 has 152).
__device__ __forceinline__ void grid_barrier(int phase) {
    __syncthreads();
    if (threadIdx.x == 0) {
        __threadfence();
        unsigned arrived = atomicAdd(&g_count, 1u) + 1u;
        unsigned want = (unsigned)(phase + 1);
        if (arrived == (unsigned)NBLOCKS * want) {
            atomicExch(&g_release, want);
        } else {
            volatile unsigned* rel = &g_release;
            while (*rel < want) { __nanosleep(64); }
        }
        __threadfence();
    }
    __syncthreads();
}

// Numerically stable sigmoid(x): never overflows, keeps relative precision
// for tiny outputs (matches JAX's stable sigmoid elementwise in fp32).
__device__ __forceinline__ float stable_sigmoid(float x) {
    float ax = fabsf(x);
    float e = __expf(-ax);                       // in (0, 1]
    float num = (x >= 0.0f) ? 1.0f : e;
    return __fdividef(num, 1.0f + e);
}

__global__ void __launch_bounds__(NTHREADS, 4)
stk_newton(const float* __restrict__ s, float* __restrict__ out) {
    extern __shared__ float thbuf[];
    __shared__ double red[NTHREADS / 32];

    float* cur = thbuf;                       // theta_t
    float* nxt = thbuf + NTHREADS * RPT;      // theta_{t+1} (uncommitted)
    const int tid = threadIdx.x;
    const unsigned gt = blockIdx.x * NTHREADS + tid;

    for (int it = 0; it < MAXIT; it++) {
        double fsum = 0.0;

        for (int i = 0; i < RPT; i++) {
            unsigned r = gt + (unsigned)i * TOTALT;
            if (r >= B_ROWS) break;                      // r grows with i
            const float4* p = reinterpret_cast<const float4*>(s) + (size_t)r * 2;
            float4 va = p[0];
            float4 vb = p[1];
            float v[8] = {va.x, va.y, va.z, va.w, vb.x, vb.y, vb.z, vb.w};

            float th;
            if (it == 0) {
                // theta0 = 3rd largest of 8 (== sorted[:, -3])
                float t1 = -3.4e38f, t2 = -3.4e38f, t3 = -3.4e38f;
                #pragma unroll
                for (int j = 0; j < 8; j++) {
                    float x = v[j];
                    if (x > t1)      { t3 = t2; t2 = t1; t1 = x; }
                    else if (x > t2) { t3 = t2; t2 = x; }
                    else if (x > t3) { t3 = x; }
                }
                th = t3;
                cur[i * NTHREADS + tid] = th;   // keep theta0 in case of iter-0 stop
            } else {
                th = cur[i * NTHREADS + tid];
            }

            // f = sum(sigmoid((v-th)/tau)) - k ;  d = sum m*(1-m)
            float sm = 0.0f, d = 0.0f;
            #pragma unroll
            for (int j = 0; j < 8; j++) {
                float x = (v[j] - th) * 100.0f;           // /tau
                float m = stable_sigmoid(x);
                sm += m;
                d  += m * (1.0f - m);
            }
            float f = sm - 2.0f;
            // theta - f/df with df = -(1/tau)*d  ->  theta + tau*f/d.
            // Guard d==0 (would only differ where the reference itself NaNs).
            float step = (d > 0.0f) ? 0.01f * __fdividef(f, d) : 0.0f;
            nxt[i * NTHREADS + tid] = th + step;
            fsum += (double)f;
        }

        // ---- block reduce fsum (double) ----
        #pragma unroll
        for (int o = 16; o > 0; o >>= 1)
            fsum += __shfl_down_sync(0xffffffffu, fsum, o);
        if ((tid & 31) == 0) red[tid >> 5] = fsum;
        __syncthreads();
        if (tid < 32) {
            double v2 = (tid < NTHREADS / 32) ? red[tid] : 0.0;
            #pragma unroll
            for (int o = 4; o > 0; o >>= 1)
                v2 += __shfl_down_sync(0xffffffffu, v2, o);
            if (tid == 0) atomicAdd(&g_accum[it], v2);
        }

        grid_barrier(it);

        // Reference checks mean(f at theta_t) BEFORE applying the update:
        // on stop, theta stays = cur (the uncommitted update in nxt is discarded).
        double total = *((volatile double*)&g_accum[it]);
        if (total * (1.0 / (double)B_ROWS) < 1.0e-3) break;

        float* t = cur; cur = nxt; nxt = t;   // commit the update
    }

    // ---- final output: sigmoid((s - theta)/tau) ----
    for (int i = 0; i < RPT; i++) {
        unsigned r = gt + (unsigned)i * TOTALT;
        if (r >= B_ROWS) break;
        const float4* p = reinterpret_cast<const float4*>(s) + (size_t)r * 2;
        float4 va = p[0];
        float4 vb = p[1];
        float v[8] = {va.x, va.y, va.z, va.w, vb.x, vb.y, vb.z, vb.w};
        float th = cur[i * NTHREADS + tid];
        float o[8];
        #pragma unroll
        for (int j = 0; j < 8; j++) {
            float x = (v[j] - th) * 100.0f;
            o[j] = stable_sigmoid(x);
        }
        float4* q = reinterpret_cast<float4*>(out) + (size_t)r * 2;
        q[0] = make_float4(o[0], o[1], o[2], o[3]);
        q[1] = make_float4(o[4], o[5], o[6], o[7]);
    }
}

extern "C" void kernel_launch(void* const* d_in, const int* in_sizes, int n_in,
                              void* d_out, int out_size) {
    (void)in_sizes; (void)n_in; (void)out_size;
    const float* s = (const float*)d_in[0];
    float* out = (float*)d_out;

    cudaFuncSetAttribute(stk_newton, cudaFuncAttributeMaxDynamicSharedMemorySize,
                         (int)SMEM_BYTES);

    stk_init<<<1, 128>>>();
    stk_newton<<<NBLOCKS, NTHREADS, SMEM_BYTES>>>(s, out);
}